// round 3
// baseline (speedup 1.0000x reference)
#include <cuda_runtime.h>
#include <math.h>

#define N_TOK 8192
#define DIMH  256
#define NOUT  513
#define SEGL  1024
#define NSEG  8
#define EPAIR 65536

typedef unsigned long long u64;

// ---------------- scratch (static device memory; no allocations) ----------------
__device__ float  g_QKL[N_TOK * NOUT];
__device__ float  g_Q[N_TOK * DIMH];
__device__ float  g_K[N_TOK * DIMH];
__device__ float  g_logit[N_TOK];
__device__ float  g_Wall[N_TOK];
__device__ float  g_logZ[N_TOK];
__device__ float  g_partM[NSEG * 8 * 8 * 128];   // (seg, rb, chunk, row)
__device__ float  g_partL[NSEG * 8 * 8 * 128];
__device__ float  g_z[NSEG];
__device__ double g_accCond;

// 36 jobs per segment: rowblock rb (128 rows), chunk ch of 2 key-tiles (64 cols each)
__constant__ unsigned char JOB_RB[36] = {
    0, 1,1, 2,2,2, 3,3,3,3, 4,4,4,4,4, 5,5,5,5,5,5,
    6,6,6,6,6,6,6, 7,7,7,7,7,7,7,7};
__constant__ unsigned char JOB_CH[36] = {
    0, 0,1, 0,1,2, 0,1,2,3, 0,1,2,3,4, 0,1,2,3,4,5,
    0,1,2,3,4,5,6, 0,1,2,3,4,5,6,7};

// ---------------- f32x2 helpers ----------------
__device__ __forceinline__ u64 pk2(float x, float y) {
    u64 r; asm("mov.b64 %0, {%1, %2};" : "=l"(r) : "f"(x), "f"(y)); return r;
}
__device__ __forceinline__ void up2(u64 v, float& x, float& y) {
    asm("mov.b64 {%0, %1}, %2;" : "=f"(x), "=f"(y) : "l"(v));
}
__device__ __forceinline__ void ffma2(u64& d, u64 a, u64 b) {
    asm("fma.rn.f32x2 %0, %1, %2, %0;" : "+l"(d) : "l"(a), "l"(b));
}

// ---------------- kernel 0: zero accumulators ----------------
__global__ void __launch_bounds__(256) zero_kernel() {
    int i = blockIdx.x * 256 + threadIdx.x;
    if (i < N_TOK) g_Wall[i] = 0.f;
    if (i == 0) g_accCond = 0.0;
}

// ---------------- kernel A: projection GEMM  C = H @ W^T + b ----------------
// 128x64 tile, 256 threads, 8x4 microtile with f32x2 (pairs along M)
__global__ void __launch_bounds__(256) proj_gemm(const float* __restrict__ A,
                                                 const float* __restrict__ W,
                                                 const float* __restrict__ bias) {
    __shared__ float As[16][132];   // [k][m], m pairs native
    __shared__ float Bd[16][136];   // [k][2*n], duplicated cols

    const int m0 = blockIdx.y * 128;
    const int n0 = blockIdx.x * 64;
    const int tid = threadIdx.x;
    const int tx = tid & 15, ty = tid >> 4;

    const int arow = tid >> 1, acolh = (tid & 1) * 8;  // A: 128 rows x 16k
    const int brow = tid >> 2, bcol = (tid & 3) * 4;   // W: 64 rows x 16k
    const bool bok = (n0 + brow) < NOUT;
    const float* Aptr = &A[(m0 + arow) * DIMH + acolh];
    const float* Wptr = bok ? &W[(n0 + brow) * DIMH + bcol] : &W[bcol];

    u64 acc[4][4];
#pragma unroll
    for (int p = 0; p < 4; p++)
#pragma unroll
        for (int c = 0; c < 4; c++) acc[p][c] = 0ull;

    for (int k0 = 0; k0 < DIMH; k0 += 16) {
        float4 a0 = *(const float4*)(Aptr + k0);
        float4 a1 = *(const float4*)(Aptr + k0 + 4);
        float4 b0 = bok ? *(const float4*)(Wptr + k0) : make_float4(0.f,0.f,0.f,0.f);
        As[acolh + 0][arow] = a0.x; As[acolh + 1][arow] = a0.y;
        As[acolh + 2][arow] = a0.z; As[acolh + 3][arow] = a0.w;
        As[acolh + 4][arow] = a1.x; As[acolh + 5][arow] = a1.y;
        As[acolh + 6][arow] = a1.z; As[acolh + 7][arow] = a1.w;
        *(u64*)&Bd[bcol + 0][2 * brow] = pk2(b0.x, b0.x);
        *(u64*)&Bd[bcol + 1][2 * brow] = pk2(b0.y, b0.y);
        *(u64*)&Bd[bcol + 2][2 * brow] = pk2(b0.z, b0.z);
        *(u64*)&Bd[bcol + 3][2 * brow] = pk2(b0.w, b0.w);
        __syncthreads();
#pragma unroll
        for (int kk = 0; kk < 16; kk++) {
            ulonglong2 qa = *(const ulonglong2*)&As[kk][ty * 8];
            ulonglong2 qb = *(const ulonglong2*)&As[kk][ty * 8 + 4];
            ulonglong2 b01 = *(const ulonglong2*)&Bd[kk][tx * 8];
            ulonglong2 b23 = *(const ulonglong2*)&Bd[kk][tx * 8 + 4];
            u64 ap[4] = {qa.x, qa.y, qb.x, qb.y};
            u64 bd[4] = {b01.x, b01.y, b23.x, b23.y};
#pragma unroll
            for (int p = 0; p < 4; p++)
#pragma unroll
                for (int c = 0; c < 4; c++) ffma2(acc[p][c], ap[p], bd[c]);
        }
        __syncthreads();
    }

#pragma unroll
    for (int p = 0; p < 4; p++) {
        int mrow = m0 + ty * 8 + 2 * p;
#pragma unroll
        for (int c = 0; c < 4; c++) {
            int n = n0 + tx * 4 + c;
            if (n < NOUT) {
                float lo, hi; up2(acc[p][c], lo, hi);
                float bv = bias[n];
                g_QKL[mrow * NOUT + n] = lo + bv;
                g_QKL[(mrow + 1) * NOUT + n] = hi + bv;
            }
        }
    }
}

// ---------------- kernel B: layernorm over 513, split into Q/K/logit ----------------
__global__ void __launch_bounds__(256) ln_kernel(const float* __restrict__ lnw,
                                                 const float* __restrict__ lnb) {
    int row = blockIdx.x;
    int tid = threadIdx.x;
    const float* x = &g_QKL[row * NOUT];
    float x0 = x[tid];
    float x1 = x[tid + 256];
    float x2 = (tid == 0) ? x[512] : 0.f;
    __shared__ float sh[8];

    float v = x0 + x1 + x2;
#pragma unroll
    for (int o = 16; o; o >>= 1) v += __shfl_xor_sync(0xffffffffu, v, o);
    if ((tid & 31) == 0) sh[tid >> 5] = v;
    __syncthreads();
    float mean = 0.f;
#pragma unroll
    for (int i = 0; i < 8; i++) mean += sh[i];
    mean *= (1.f / 513.f);
    __syncthreads();

    float d0 = x0 - mean, d1 = x1 - mean, d2 = x2 - mean;
    v = d0 * d0 + d1 * d1 + ((tid == 0) ? d2 * d2 : 0.f);
#pragma unroll
    for (int o = 16; o; o >>= 1) v += __shfl_xor_sync(0xffffffffu, v, o);
    if ((tid & 31) == 0) sh[tid >> 5] = v;
    __syncthreads();
    float var = 0.f;
#pragma unroll
    for (int i = 0; i < 8; i++) var += sh[i];
    var *= (1.f / 513.f);
    float rstd = rsqrtf(var + 1e-5f);

    g_Q[row * DIMH + tid] = d0 * rstd * lnw[tid] + lnb[tid];
    g_K[row * DIMH + tid] = d1 * rstd * lnw[tid + 256] + lnb[tid + 256];
    if (tid == 0) g_logit[row] = d2 * rstd * lnw[512] + lnb[512];
}

// ---------------- kernel C: scatter-add weights ----------------
__global__ void __launch_bounds__(256) scatter_kernel(const float* __restrict__ wts,
                                                      const int* __restrict__ ii) {
    int e = blockIdx.x * 256 + threadIdx.x;
    if (e < EPAIR) atomicAdd(&g_Wall[ii[e]], wts[e]);
}

// ---------------- kernel D: causal attention partial logsumexp ----------------
// block = (seg, rowblock of 128 rows, chunk of up to 2 key-tiles of 64)
// Epilogue is fully branch-free: no divergent __shfl_sync (round-2 hang fix).
__global__ void __launch_bounds__(256) attn_partial() {
    int bx = blockIdx.x;
    int seg = bx / 36;
    int jid = bx - seg * 36;
    int rb = JOB_RB[jid];
    int ch = JOB_CH[jid];
    int kt_begin = ch * 2;
    int kt_end = min(ch * 2 + 2, 2 * rb + 2);

    const int tid = threadIdx.x;
    const int tx = tid & 15, ty = tid >> 4;
    __shared__ float Qs[16][132];
    __shared__ float Kd[16][136];

    const int base = seg * SEGL;
    const int qrow = tid >> 1, qcolh = (tid & 1) * 8;
    const int krow = tid >> 2, kcol = (tid & 3) * 4;
    const float* Qptr = &g_Q[(base + rb * 128 + qrow) * DIMH + qcolh];

    float m_run[8], l_run[8];
#pragma unroll
    for (int r = 0; r < 8; r++) { m_run[r] = -INFINITY; l_run[r] = 0.f; }

    const int irow_base = rb * 128 + ty * 8;   // within segment

    for (int kt = kt_begin; kt < kt_end; kt++) {
        const float* Kptr = &g_K[(base + kt * 64 + krow) * DIMH + kcol];
        u64 acc[4][4];
#pragma unroll
        for (int p = 0; p < 4; p++)
#pragma unroll
            for (int c = 0; c < 4; c++) acc[p][c] = 0ull;

        for (int k0 = 0; k0 < DIMH; k0 += 16) {
            float4 a0 = *(const float4*)(Qptr + k0);
            float4 a1 = *(const float4*)(Qptr + k0 + 4);
            float4 b0 = *(const float4*)(Kptr + k0);
            Qs[qcolh + 0][qrow] = a0.x; Qs[qcolh + 1][qrow] = a0.y;
            Qs[qcolh + 2][qrow] = a0.z; Qs[qcolh + 3][qrow] = a0.w;
            Qs[qcolh + 4][qrow] = a1.x; Qs[qcolh + 5][qrow] = a1.y;
            Qs[qcolh + 6][qrow] = a1.z; Qs[qcolh + 7][qrow] = a1.w;
            *(u64*)&Kd[kcol + 0][2 * krow] = pk2(b0.x, b0.x);
            *(u64*)&Kd[kcol + 1][2 * krow] = pk2(b0.y, b0.y);
            *(u64*)&Kd[kcol + 2][2 * krow] = pk2(b0.z, b0.z);
            *(u64*)&Kd[kcol + 3][2 * krow] = pk2(b0.w, b0.w);
            __syncthreads();
#pragma unroll
            for (int kk = 0; kk < 16; kk++) {
                ulonglong2 qa = *(const ulonglong2*)&Qs[kk][ty * 8];
                ulonglong2 qb = *(const ulonglong2*)&Qs[kk][ty * 8 + 4];
                ulonglong2 b01 = *(const ulonglong2*)&Kd[kk][tx * 8];
                ulonglong2 b23 = *(const ulonglong2*)&Kd[kk][tx * 8 + 4];
                u64 ap[4] = {qa.x, qa.y, qb.x, qb.y};
                u64 bd[4] = {b01.x, b01.y, b23.x, b23.y};
#pragma unroll
                for (int p = 0; p < 4; p++)
#pragma unroll
                    for (int c = 0; c < 4; c++) ffma2(acc[p][c], ap[p], bd[c]);
            }
            __syncthreads();
        }

        // epilogue: mask (j < i) + online logsumexp, branch-free
#pragma unroll
        for (int p = 0; p < 4; p++) {
            float s[2][4];
#pragma unroll
            for (int c = 0; c < 4; c++) up2(acc[p][c], s[0][c], s[1][c]);
#pragma unroll
            for (int h = 0; h < 2; h++) {
                int r = 2 * p + h;
                int irow = irow_base + r;
                float mx = -INFINITY;
#pragma unroll
                for (int c = 0; c < 4; c++) {
                    int jcol = kt * 64 + tx * 4 + c;
                    if (jcol >= irow) s[h][c] = -INFINITY;
                    mx = fmaxf(mx, s[h][c]);
                }
#pragma unroll
                for (int o = 8; o; o >>= 1) mx = fmaxf(mx, __shfl_xor_sync(0xffffffffu, mx, o));
                float m_new = fmaxf(m_run[r], mx);
                // mb: finite stand-in for m_new when the whole row is masked,
                // so expf(-inf - mb) == 0 and no NaNs arise.
                float mb = fmaxf(m_new, -3.0e38f);
                float ssum = 0.f;
#pragma unroll
                for (int c = 0; c < 4; c++) ssum += __expf(s[h][c] - mb);
#pragma unroll
                for (int o = 8; o; o >>= 1) ssum += __shfl_xor_sync(0xffffffffu, ssum, o);
                float scale = (l_run[r] > 0.f) ? __expf(m_run[r] - mb) : 0.f;
                l_run[r] = l_run[r] * scale + ssum;
                m_run[r] = m_new;
            }
        }
    }

    if (tx == 0) {
        int pbase = ((seg * 8 + rb) * 8 + ch) * 128;
#pragma unroll
        for (int r = 0; r < 8; r++) {
            g_partM[pbase + ty * 8 + r] = m_run[r];
            g_partL[pbase + ty * 8 + r] = l_run[r];
        }
    }
}

// ---------------- kernel D2: merge chunk partials into logZ ----------------
__global__ void __launch_bounds__(256) combine_kernel() {
    int i = blockIdx.x * 256 + threadIdx.x;
    if (i >= N_TOK) return;
    int seg = i >> 10;
    int r = i & 1023;
    int rb = r >> 7;
    int rr = r & 127;
    int nch = rb + 1;
    float M = -INFINITY, L = 0.f;
    for (int ch = 0; ch < nch; ch++) {
        int p = ((seg * 8 + rb) * 8 + ch) * 128 + rr;
        float m = g_partM[p];
        float l = g_partL[p];
        if (l > 0.f) {
            if (m > M) { L = L * __expf(M - m) + l; M = m; }
            else        { L += l * __expf(m - M); }
        }
    }
    g_logZ[i] = (L > 0.f) ? (M + logf(L)) : -INFINITY;
}

// ---------------- kernel E: sum_e w[e] * (Q[i[e]] . K[j[e]]) ----------------
__global__ void __launch_bounds__(256) cond_kernel(const float* __restrict__ wts,
                                                   const int* __restrict__ ii,
                                                   const int* __restrict__ jj) {
    int tid = threadIdx.x;
    int lane = tid & 31;
    int warp = tid >> 5;
    int gw = blockIdx.x * 8 + warp;
    double acc = 0.0;
    for (int e = gw; e < EPAIR; e += 2048) {
        int i = ii[e], j = jj[e];
        const float4* q = (const float4*)&g_Q[i * DIMH];
        const float4* k = (const float4*)&g_K[j * DIMH];
        float4 qa = q[lane * 2], qb = q[lane * 2 + 1];
        float4 ka = k[lane * 2], kb = k[lane * 2 + 1];
        float d = qa.x * ka.x + qa.y * ka.y + qa.z * ka.z + qa.w * ka.w
                + qb.x * kb.x + qb.y * kb.y + qb.z * kb.z + qb.w * kb.w;
#pragma unroll
        for (int o = 16; o; o >>= 1) d += __shfl_xor_sync(0xffffffffu, d, o);
        if (lane == 0) acc += (double)wts[e] * (double)d;
    }
    __shared__ double shd[256];
    shd[tid] = acc;
    __syncthreads();
    for (int s = 128; s; s >>= 1) {
        if (tid < s) shd[tid] += shd[tid + s];
        __syncthreads();
    }
    if (tid == 0) atomicAdd(&g_accCond, shd[0]);
}

// ---------------- kernel F: per-segment logsumexp of logit ----------------
__global__ void __launch_bounds__(256) zseg_kernel() {
    int seg = blockIdx.x;
    int tid = threadIdx.x;
    const float* lp = &g_logit[seg * SEGL];
    float vals[4];
    float mx = -INFINITY;
#pragma unroll
    for (int q = 0; q < 4; q++) { vals[q] = lp[tid + q * 256]; mx = fmaxf(mx, vals[q]); }
    __shared__ float sh[8];
#pragma unroll
    for (int o = 16; o; o >>= 1) mx = fmaxf(mx, __shfl_xor_sync(0xffffffffu, mx, o));
    if ((tid & 31) == 0) sh[tid >> 5] = mx;
    __syncthreads();
    float bm = -INFINITY;
#pragma unroll
    for (int i = 0; i < 8; i++) bm = fmaxf(bm, sh[i]);
    __syncthreads();
    float s = 0.f;
#pragma unroll
    for (int q = 0; q < 4; q++) s += expf(vals[q] - bm);
#pragma unroll
    for (int o = 16; o; o >>= 1) s += __shfl_xor_sync(0xffffffffu, s, o);
    if ((tid & 31) == 0) sh[tid >> 5] = s;
    __syncthreads();
    if (tid == 0) {
        float tot = 0.f;
#pragma unroll
        for (int i = 0; i < 8; i++) tot += sh[i];
        g_z[seg] = bm + logf(tot);
    }
}

// ---------------- kernel G: final reduction ----------------
__global__ void __launch_bounds__(256) final_kernel(float* __restrict__ out) {
    int tid = threadIdx.x;
    double acc = 0.0;
    for (int i = tid; i < N_TOK; i += 256) {
        float w = g_Wall[i];
        if (w > 0.f) {
            int seg = i >> 10;
            acc += (double)w * ((double)g_logit[i] - (double)g_z[seg] - (double)g_logZ[i]);
        }
    }
    __shared__ double shd[256];
    shd[tid] = acc;
    __syncthreads();
    for (int s = 128; s; s >>= 1) {
        if (tid < s) shd[tid] += shd[tid + s];
        __syncthreads();
    }
    if (tid == 0) out[0] = -(float)(g_accCond + shd[0]);
}

// ---------------- launch ----------------
extern "C" void kernel_launch(void* const* d_in, const int* in_sizes, int n_in,
                              void* d_out, int out_size) {
    const float* hidden = (const float*)d_in[0];
    const float* Wp     = (const float*)d_in[1];
    const float* bp     = (const float*)d_in[2];
    const float* lnw    = (const float*)d_in[3];
    const float* lnb    = (const float*)d_in[4];
    const float* wts    = (const float*)d_in[5];
    const int*   ii     = (const int*)d_in[6];
    const int*   jj     = (const int*)d_in[7];
    float* out = (float*)d_out;

    zero_kernel<<<32, 256>>>();
    proj_gemm<<<dim3(9, 64), 256>>>(hidden, Wp, bp);
    ln_kernel<<<N_TOK, 256>>>(lnw, lnb);
    scatter_kernel<<<256, 256>>>(wts, ii);
    attn_partial<<<288, 256>>>();
    combine_kernel<<<32, 256>>>();
    cond_kernel<<<256, 256>>>(wts, ii, jj);
    zseg_kernel<<<NSEG, 256>>>();
    final_kernel<<<1, 256>>>(out);
}

// round 4
// speedup vs baseline: 2.4864x; 2.4864x over previous
#include <cuda_runtime.h>
#include <math.h>
#include <stdint.h>

#define N_TOK 8192
#define DIMH  256
#define NOUT  513
#define SEGL  1024
#define NSEG  8
#define EPAIR 65536

// ---------------- scratch (static device memory; no allocations) ----------------
__device__ float  g_QKL[N_TOK * NOUT];
__device__ float  g_Q[N_TOK * DIMH];
__device__ float  g_K[N_TOK * DIMH];
__device__ float  g_logit[N_TOK];
__device__ float  g_Wall[N_TOK];
__device__ float  g_logZ[N_TOK];
__device__ float  g_partM[NSEG * 8 * 8 * 128];   // (seg, rb, chunk, row)
__device__ float  g_partL[NSEG * 8 * 8 * 128];
__device__ float  g_z[NSEG];
__device__ double g_accCond;

// 36 jobs per segment: rowblock rb (128 rows) x keyblock ch (128 cols), ch <= rb
__constant__ unsigned char JOB_RB[36] = {
    0, 1,1, 2,2,2, 3,3,3,3, 4,4,4,4,4, 5,5,5,5,5,5,
    6,6,6,6,6,6,6, 7,7,7,7,7,7,7,7};
__constant__ unsigned char JOB_CH[36] = {
    0, 0,1, 0,1,2, 0,1,2,3, 0,1,2,3,4, 0,1,2,3,4,5,
    0,1,2,3,4,5,6, 0,1,2,3,4,5,6,7};

// ---------------- tf32 helpers ----------------
__device__ __forceinline__ uint32_t tf32cvt(float x) {
    uint32_t r; asm("cvt.rna.tf32.f32 %0, %1;" : "=r"(r) : "f"(x)); return r;
}
__device__ __forceinline__ void mma_tf32(float* c, uint32_t a0, uint32_t a1,
                                         uint32_t a2, uint32_t a3,
                                         uint32_t b0, uint32_t b1) {
    asm("mma.sync.aligned.m16n8k8.row.col.f32.tf32.tf32.f32 "
        "{%0,%1,%2,%3},{%4,%5,%6,%7},{%8,%9},{%0,%1,%2,%3};"
        : "+f"(c[0]), "+f"(c[1]), "+f"(c[2]), "+f"(c[3])
        : "r"(a0), "r"(a1), "r"(a2), "r"(a3), "r"(b0), "r"(b1));
}

// ---------------- kernel 0: zero accumulators ----------------
__global__ void __launch_bounds__(256) zero_kernel() {
    int i = blockIdx.x * 256 + threadIdx.x;
    if (i < N_TOK) g_Wall[i] = 0.f;
    if (i == 0) g_accCond = 0.0;
}

// ---------------- kernel A: projection GEMM (tf32 tensor cores) ----------------
// C[m][n] = sum_k H[m][k]*W[n][k] + b[n]; tile 128x64, 8 warps, warp = 16x64
__global__ void __launch_bounds__(256) proj_gemm_tc(const float* __restrict__ A,
                                                    const float* __restrict__ W,
                                                    const float* __restrict__ bias) {
    __shared__ uint32_t As[128][36];
    __shared__ uint32_t Bs[64][36];
    const int m0 = blockIdx.y * 128;
    const int n0 = blockIdx.x * 64;
    const int tid = threadIdx.x;
    const int wid = tid >> 5, lane = tid & 31;
    const int g = lane >> 2, tig = lane & 3;

    float acc[8][4];
#pragma unroll
    for (int nt = 0; nt < 8; nt++)
#pragma unroll
        for (int e = 0; e < 4; e++) acc[nt][e] = 0.f;

    for (int k0 = 0; k0 < DIMH; k0 += 32) {
#pragma unroll
        for (int i = 0; i < 4; i++) {
            int idx = tid + i * 256;            // 0..1023
            int r = idx >> 3, c4 = (idx & 7) * 4;
            float4 v = *(const float4*)&A[(m0 + r) * DIMH + k0 + c4];
            As[r][c4 + 0] = tf32cvt(v.x); As[r][c4 + 1] = tf32cvt(v.y);
            As[r][c4 + 2] = tf32cvt(v.z); As[r][c4 + 3] = tf32cvt(v.w);
        }
#pragma unroll
        for (int i = 0; i < 2; i++) {
            int idx = tid + i * 256;            // 0..511
            int r = idx >> 3, c4 = (idx & 7) * 4;
            int n = n0 + r;
            float4 v = (n < NOUT) ? *(const float4*)&W[n * DIMH + k0 + c4]
                                  : make_float4(0.f, 0.f, 0.f, 0.f);
            Bs[r][c4 + 0] = tf32cvt(v.x); Bs[r][c4 + 1] = tf32cvt(v.y);
            Bs[r][c4 + 2] = tf32cvt(v.z); Bs[r][c4 + 3] = tf32cvt(v.w);
        }
        __syncthreads();
#pragma unroll
        for (int ks = 0; ks < 4; ks++) {
            int kb = ks * 8;
            uint32_t a0 = As[wid * 16 + g][kb + tig];
            uint32_t a1 = As[wid * 16 + g + 8][kb + tig];
            uint32_t a2 = As[wid * 16 + g][kb + tig + 4];
            uint32_t a3 = As[wid * 16 + g + 8][kb + tig + 4];
#pragma unroll
            for (int nt = 0; nt < 8; nt++) {
                uint32_t b0 = Bs[nt * 8 + g][kb + tig];
                uint32_t b1 = Bs[nt * 8 + g][kb + tig + 4];
                mma_tf32(acc[nt], a0, a1, a2, a3, b0, b1);
            }
        }
        __syncthreads();
    }

    const int r0 = m0 + wid * 16 + g;
#pragma unroll
    for (int nt = 0; nt < 8; nt++) {
        int c0 = n0 + nt * 8 + tig * 2;
        if (c0 < NOUT) {
            float bv = bias[c0];
            g_QKL[r0 * NOUT + c0] = acc[nt][0] + bv;
            g_QKL[(r0 + 8) * NOUT + c0] = acc[nt][2] + bv;
        }
        if (c0 + 1 < NOUT) {
            float bv = bias[c0 + 1];
            g_QKL[r0 * NOUT + c0 + 1] = acc[nt][1] + bv;
            g_QKL[(r0 + 8) * NOUT + c0 + 1] = acc[nt][3] + bv;
        }
    }
}

// ---------------- kernel B: layernorm over 513, split into Q/K/logit ----------------
__global__ void __launch_bounds__(256) ln_kernel(const float* __restrict__ lnw,
                                                 const float* __restrict__ lnb) {
    int row = blockIdx.x;
    int tid = threadIdx.x;
    const float* x = &g_QKL[row * NOUT];
    float x0 = x[tid];
    float x1 = x[tid + 256];
    float x2 = (tid == 0) ? x[512] : 0.f;
    __shared__ float sh[8];

    float v = x0 + x1 + x2;
#pragma unroll
    for (int o = 16; o; o >>= 1) v += __shfl_xor_sync(0xffffffffu, v, o);
    if ((tid & 31) == 0) sh[tid >> 5] = v;
    __syncthreads();
    float mean = 0.f;
#pragma unroll
    for (int i = 0; i < 8; i++) mean += sh[i];
    mean *= (1.f / 513.f);
    __syncthreads();

    float d0 = x0 - mean, d1 = x1 - mean, d2 = x2 - mean;
    v = d0 * d0 + d1 * d1 + ((tid == 0) ? d2 * d2 : 0.f);
#pragma unroll
    for (int o = 16; o; o >>= 1) v += __shfl_xor_sync(0xffffffffu, v, o);
    if ((tid & 31) == 0) sh[tid >> 5] = v;
    __syncthreads();
    float var = 0.f;
#pragma unroll
    for (int i = 0; i < 8; i++) var += sh[i];
    var *= (1.f / 513.f);
    float rstd = rsqrtf(var + 1e-5f);

    g_Q[row * DIMH + tid] = d0 * rstd * lnw[tid] + lnb[tid];
    g_K[row * DIMH + tid] = d1 * rstd * lnw[tid + 256] + lnb[tid + 256];
    if (tid == 0) g_logit[row] = d2 * rstd * lnw[512] + lnb[512];
}

// ---------------- kernel C: scatter-add weights ----------------
__global__ void __launch_bounds__(256) scatter_kernel(const float* __restrict__ wts,
                                                      const int* __restrict__ ii) {
    int e = blockIdx.x * 256 + threadIdx.x;
    if (e < EPAIR) atomicAdd(&g_Wall[ii[e]], wts[e]);
}

// ---------------- kernel D: causal attention partial LSE (tf32 tensor cores) ----------------
// job = (seg, rowblock rb: 128 rows, keyblock ch: 128 cols), ch <= rb
__global__ void __launch_bounds__(256) attn_tc() {
    int bx = blockIdx.x;
    int seg = bx / 36;
    int jid = bx - seg * 36;
    int rb = JOB_RB[jid];
    int ch = JOB_CH[jid];

    __shared__ uint32_t Qs[128][36];
    __shared__ uint32_t Ks[128][36];
    const int tid = threadIdx.x;
    const int wid = tid >> 5, lane = tid & 31;
    const int g = lane >> 2, tig = lane & 3;
    const int base = seg * SEGL;

    float acc[16][4];
#pragma unroll
    for (int nt = 0; nt < 16; nt++)
#pragma unroll
        for (int e = 0; e < 4; e++) acc[nt][e] = 0.f;

    for (int k0 = 0; k0 < DIMH; k0 += 32) {
#pragma unroll
        for (int i = 0; i < 4; i++) {
            int idx = tid + i * 256;
            int r = idx >> 3, c4 = (idx & 7) * 4;
            float4 q = *(const float4*)&g_Q[(base + rb * 128 + r) * DIMH + k0 + c4];
            float4 k = *(const float4*)&g_K[(base + ch * 128 + r) * DIMH + k0 + c4];
            Qs[r][c4 + 0] = tf32cvt(q.x); Qs[r][c4 + 1] = tf32cvt(q.y);
            Qs[r][c4 + 2] = tf32cvt(q.z); Qs[r][c4 + 3] = tf32cvt(q.w);
            Ks[r][c4 + 0] = tf32cvt(k.x); Ks[r][c4 + 1] = tf32cvt(k.y);
            Ks[r][c4 + 2] = tf32cvt(k.z); Ks[r][c4 + 3] = tf32cvt(k.w);
        }
        __syncthreads();
#pragma unroll
        for (int ks = 0; ks < 4; ks++) {
            int kb = ks * 8;
            uint32_t a0 = Qs[wid * 16 + g][kb + tig];
            uint32_t a1 = Qs[wid * 16 + g + 8][kb + tig];
            uint32_t a2 = Qs[wid * 16 + g][kb + tig + 4];
            uint32_t a3 = Qs[wid * 16 + g + 8][kb + tig + 4];
#pragma unroll
            for (int nt = 0; nt < 16; nt++) {
                uint32_t b0 = Ks[nt * 8 + g][kb + tig];
                uint32_t b1 = Ks[nt * 8 + g][kb + tig + 4];
                mma_tf32(acc[nt], a0, a1, a2, a3, b0, b1);
            }
        }
        __syncthreads();
    }

    // epilogue: causal mask + per-row logsumexp partials (uniform control flow)
    const int pbase = ((seg * 8 + rb) * 8 + ch) * 128;
    const int rin0 = wid * 16 + g;
#pragma unroll
    for (int h = 0; h < 2; h++) {
        int rin = rin0 + h * 8;
        int irow = rb * 128 + rin;           // row index within segment
        float mx = -INFINITY;
#pragma unroll
        for (int nt = 0; nt < 16; nt++) {
#pragma unroll
            for (int e = 0; e < 2; e++) {
                int jcol = ch * 128 + nt * 8 + tig * 2 + e;
                float v = acc[nt][h * 2 + e];
                if (jcol >= irow) v = -INFINITY;
                acc[nt][h * 2 + e] = v;
                mx = fmaxf(mx, v);
            }
        }
        mx = fmaxf(mx, __shfl_xor_sync(0xffffffffu, mx, 1));
        mx = fmaxf(mx, __shfl_xor_sync(0xffffffffu, mx, 2));
        float mb = fmaxf(mx, -3.0e38f);
        float s = 0.f;
#pragma unroll
        for (int nt = 0; nt < 16; nt++) {
            s += __expf(acc[nt][h * 2 + 0] - mb);
            s += __expf(acc[nt][h * 2 + 1] - mb);
        }
        s += __shfl_xor_sync(0xffffffffu, s, 1);
        s += __shfl_xor_sync(0xffffffffu, s, 2);
        if (tig == 0) {
            g_partM[pbase + rin] = mx;
            g_partL[pbase + rin] = s;
        }
    }
}

// ---------------- kernel D2: merge chunk partials into logZ ----------------
__global__ void __launch_bounds__(256) combine_kernel() {
    int i = blockIdx.x * 256 + threadIdx.x;
    if (i >= N_TOK) return;
    int seg = i >> 10;
    int r = i & 1023;
    int rb = r >> 7;
    int rr = r & 127;
    int nch = rb + 1;
    float M = -INFINITY, L = 0.f;
    for (int ch = 0; ch < nch; ch++) {
        int p = ((seg * 8 + rb) * 8 + ch) * 128 + rr;
        float m = g_partM[p];
        float l = g_partL[p];
        if (l > 0.f) {
            if (m > M) { L = L * __expf(M - m) + l; M = m; }
            else        { L += l * __expf(m - M); }
        }
    }
    g_logZ[i] = (L > 0.f) ? (M + logf(L)) : -INFINITY;
}

// ---------------- kernel E: sum_e w[e] * (Q[i[e]] . K[j[e]])  (fp32 exact) ----------------
__global__ void __launch_bounds__(256) cond_kernel(const float* __restrict__ wts,
                                                   const int* __restrict__ ii,
                                                   const int* __restrict__ jj) {
    int tid = threadIdx.x;
    int lane = tid & 31;
    int warp = tid >> 5;
    int gw = blockIdx.x * 8 + warp;
    double acc = 0.0;
    for (int e = gw; e < EPAIR; e += 2048) {
        int i = ii[e], j = jj[e];
        const float4* q = (const float4*)&g_Q[i * DIMH];
        const float4* k = (const float4*)&g_K[j * DIMH];
        float4 qa = q[lane * 2], qb = q[lane * 2 + 1];
        float4 ka = k[lane * 2], kb = k[lane * 2 + 1];
        float d = qa.x * ka.x + qa.y * ka.y + qa.z * ka.z + qa.w * ka.w
                + qb.x * kb.x + qb.y * kb.y + qb.z * kb.z + qb.w * kb.w;
#pragma unroll
        for (int o = 16; o; o >>= 1) d += __shfl_xor_sync(0xffffffffu, d, o);
        if (lane == 0) acc += (double)wts[e] * (double)d;
    }
    __shared__ double shd[256];
    shd[tid] = acc;
    __syncthreads();
    for (int s = 128; s; s >>= 1) {
        if (tid < s) shd[tid] += shd[tid + s];
        __syncthreads();
    }
    if (tid == 0) atomicAdd(&g_accCond, shd[0]);
}

// ---------------- kernel F: per-segment logsumexp of logit ----------------
__global__ void __launch_bounds__(256) zseg_kernel() {
    int seg = blockIdx.x;
    int tid = threadIdx.x;
    const float* lp = &g_logit[seg * SEGL];
    float vals[4];
    float mx = -INFINITY;
#pragma unroll
    for (int q = 0; q < 4; q++) { vals[q] = lp[tid + q * 256]; mx = fmaxf(mx, vals[q]); }
    __shared__ float sh[8];
#pragma unroll
    for (int o = 16; o; o >>= 1) mx = fmaxf(mx, __shfl_xor_sync(0xffffffffu, mx, o));
    if ((tid & 31) == 0) sh[tid >> 5] = mx;
    __syncthreads();
    float bm = -INFINITY;
#pragma unroll
    for (int i = 0; i < 8; i++) bm = fmaxf(bm, sh[i]);
    __syncthreads();
    float s = 0.f;
#pragma unroll
    for (int q = 0; q < 4; q++) s += expf(vals[q] - bm);
#pragma unroll
    for (int o = 16; o; o >>= 1) s += __shfl_xor_sync(0xffffffffu, s, o);
    if ((tid & 31) == 0) sh[tid >> 5] = s;
    __syncthreads();
    if (tid == 0) {
        float tot = 0.f;
#pragma unroll
        for (int i = 0; i < 8; i++) tot += sh[i];
        g_z[seg] = bm + logf(tot);
    }
}

// ---------------- kernel G: final reduction ----------------
__global__ void __launch_bounds__(256) final_kernel(float* __restrict__ out) {
    int tid = threadIdx.x;
    double acc = 0.0;
    for (int i = tid; i < N_TOK; i += 256) {
        float w = g_Wall[i];
        if (w > 0.f) {
            int seg = i >> 10;
            acc += (double)w * ((double)g_logit[i] - (double)g_z[seg] - (double)g_logZ[i]);
        }
    }
    __shared__ double shd[256];
    shd[tid] = acc;
    __syncthreads();
    for (int s = 128; s; s >>= 1) {
        if (tid < s) shd[tid] += shd[tid + s];
        __syncthreads();
    }
    if (tid == 0) out[0] = -(float)(g_accCond + shd[0]);
}

// ---------------- launch ----------------
extern "C" void kernel_launch(void* const* d_in, const int* in_sizes, int n_in,
                              void* d_out, int out_size) {
    const float* hidden = (const float*)d_in[0];
    const float* Wp     = (const float*)d_in[1];
    const float* bp     = (const float*)d_in[2];
    const float* lnw    = (const float*)d_in[3];
    const float* lnb    = (const float*)d_in[4];
    const float* wts    = (const float*)d_in[5];
    const int*   ii     = (const int*)d_in[6];
    const int*   jj     = (const int*)d_in[7];
    float* out = (float*)d_out;

    zero_kernel<<<32, 256>>>();
    proj_gemm_tc<<<dim3(9, 64), 256>>>(hidden, Wp, bp);
    ln_kernel<<<N_TOK, 256>>>(lnw, lnb);
    scatter_kernel<<<256, 256>>>(wts, ii);
    attn_tc<<<288, 256>>>();
    combine_kernel<<<32, 256>>>();
    cond_kernel<<<256, 256>>>(wts, ii, jj);
    zseg_kernel<<<NSEG, 256>>>();
    final_kernel<<<1, 256>>>(out);
}

// round 6
// speedup vs baseline: 2.6227x; 1.0548x over previous
#include <cuda_runtime.h>
#include <cuda_bf16.h>
#include <math.h>
#include <stdint.h>

#define N_TOK 8192
#define DIMH  256
#define NOUT  513
#define SEGL  1024
#define NSEG  8
#define EPAIR 65536

// ---------------- scratch (static device memory; no allocations) ----------------
__device__ float  g_QKL[N_TOK * NOUT];
__device__ float  g_Q[N_TOK * DIMH];
__device__ float  g_K[N_TOK * DIMH];
__device__ __nv_bfloat16 g_Qh[N_TOK * DIMH];
__device__ __nv_bfloat16 g_Kh[N_TOK * DIMH];
__device__ float  g_logit[N_TOK];
__device__ float  g_Wall[N_TOK];
__device__ float  g_logZ[N_TOK];
__device__ float  g_partM[NSEG * 8 * 8 * 128];   // (seg, rb, chunk, row)
__device__ float  g_partL[NSEG * 8 * 8 * 128];
__device__ float  g_z[NSEG];
__device__ double g_accCond;

// 36 jobs per segment: rowblock rb (128 rows) x keyblock ch (128 cols), ch <= rb
__constant__ unsigned char JOB_RB[36] = {
    0, 1,1, 2,2,2, 3,3,3,3, 4,4,4,4,4, 5,5,5,5,5,5,
    6,6,6,6,6,6,6, 7,7,7,7,7,7,7,7};
__constant__ unsigned char JOB_CH[36] = {
    0, 0,1, 0,1,2, 0,1,2,3, 0,1,2,3,4, 0,1,2,3,4,5,
    0,1,2,3,4,5,6, 0,1,2,3,4,5,6,7};

// ---------------- mma helpers ----------------
__device__ __forceinline__ uint32_t tf32cvt(float x) {
    uint32_t r; asm("cvt.rna.tf32.f32 %0, %1;" : "=r"(r) : "f"(x)); return r;
}
__device__ __forceinline__ void mma_tf32(float* c, uint32_t a0, uint32_t a1,
                                         uint32_t a2, uint32_t a3,
                                         uint32_t b0, uint32_t b1) {
    asm("mma.sync.aligned.m16n8k8.row.col.f32.tf32.tf32.f32 "
        "{%0,%1,%2,%3},{%4,%5,%6,%7},{%8,%9},{%0,%1,%2,%3};"
        : "+f"(c[0]), "+f"(c[1]), "+f"(c[2]), "+f"(c[3])
        : "r"(a0), "r"(a1), "r"(a2), "r"(a3), "r"(b0), "r"(b1));
}
__device__ __forceinline__ void mma_bf16(float* c, uint32_t a0, uint32_t a1,
                                         uint32_t a2, uint32_t a3,
                                         uint32_t b0, uint32_t b1) {
    asm("mma.sync.aligned.m16n8k16.row.col.f32.bf16.bf16.f32 "
        "{%0,%1,%2,%3},{%4,%5,%6,%7},{%8,%9},{%0,%1,%2,%3};"
        : "+f"(c[0]), "+f"(c[1]), "+f"(c[2]), "+f"(c[3])
        : "r"(a0), "r"(a1), "r"(a2), "r"(a3), "r"(b0), "r"(b1));
}

// ---------------- kernel 0: zero accumulators ----------------
__global__ void __launch_bounds__(256) zero_kernel() {
    int i = blockIdx.x * 256 + threadIdx.x;
    if (i < N_TOK) g_Wall[i] = 0.f;
    if (i == 0) g_accCond = 0.0;
}

// ---------------- kernel A: projection GEMM (tf32 tensor cores) ----------------
__global__ void __launch_bounds__(256) proj_gemm_tc(const float* __restrict__ A,
                                                    const float* __restrict__ W,
                                                    const float* __restrict__ bias) {
    __shared__ uint32_t As[128][36];
    __shared__ uint32_t Bs[64][36];
    const int m0 = blockIdx.y * 128;
    const int n0 = blockIdx.x * 64;
    const int tid = threadIdx.x;
    const int wid = tid >> 5, lane = tid & 31;
    const int g = lane >> 2, tig = lane & 3;

    float acc[8][4];
#pragma unroll
    for (int nt = 0; nt < 8; nt++)
#pragma unroll
        for (int e = 0; e < 4; e++) acc[nt][e] = 0.f;

    for (int k0 = 0; k0 < DIMH; k0 += 32) {
#pragma unroll
        for (int i = 0; i < 4; i++) {
            int idx = tid + i * 256;
            int r = idx >> 3, c4 = (idx & 7) * 4;
            float4 v = *(const float4*)&A[(m0 + r) * DIMH + k0 + c4];
            As[r][c4 + 0] = tf32cvt(v.x); As[r][c4 + 1] = tf32cvt(v.y);
            As[r][c4 + 2] = tf32cvt(v.z); As[r][c4 + 3] = tf32cvt(v.w);
        }
#pragma unroll
        for (int i = 0; i < 2; i++) {
            int idx = tid + i * 256;
            int r = idx >> 3, c4 = (idx & 7) * 4;
            int n = n0 + r;
            float4 v = (n < NOUT) ? *(const float4*)&W[n * DIMH + k0 + c4]
                                  : make_float4(0.f, 0.f, 0.f, 0.f);
            Bs[r][c4 + 0] = tf32cvt(v.x); Bs[r][c4 + 1] = tf32cvt(v.y);
            Bs[r][c4 + 2] = tf32cvt(v.z); Bs[r][c4 + 3] = tf32cvt(v.w);
        }
        __syncthreads();
#pragma unroll
        for (int ks = 0; ks < 4; ks++) {
            int kb = ks * 8;
            uint32_t a0 = As[wid * 16 + g][kb + tig];
            uint32_t a1 = As[wid * 16 + g + 8][kb + tig];
            uint32_t a2 = As[wid * 16 + g][kb + tig + 4];
            uint32_t a3 = As[wid * 16 + g + 8][kb + tig + 4];
#pragma unroll
            for (int nt = 0; nt < 8; nt++) {
                uint32_t b0 = Bs[nt * 8 + g][kb + tig];
                uint32_t b1 = Bs[nt * 8 + g][kb + tig + 4];
                mma_tf32(acc[nt], a0, a1, a2, a3, b0, b1);
            }
        }
        __syncthreads();
    }

    const int r0 = m0 + wid * 16 + g;
#pragma unroll
    for (int nt = 0; nt < 8; nt++) {
        int c0 = n0 + nt * 8 + tig * 2;
        if (c0 < NOUT) {
            float bv = bias[c0];
            g_QKL[r0 * NOUT + c0] = acc[nt][0] + bv;
            g_QKL[(r0 + 8) * NOUT + c0] = acc[nt][2] + bv;
        }
        if (c0 + 1 < NOUT) {
            float bv = bias[c0 + 1];
            g_QKL[r0 * NOUT + c0 + 1] = acc[nt][1] + bv;
            g_QKL[(r0 + 8) * NOUT + c0 + 1] = acc[nt][3] + bv;
        }
    }
}

// ---------------- kernel B: layernorm; writes Q/K (fp32 + bf16) and logit ----------------
__global__ void __launch_bounds__(256) ln_kernel(const float* __restrict__ lnw,
                                                 const float* __restrict__ lnb) {
    int row = blockIdx.x;
    int tid = threadIdx.x;
    const float* x = &g_QKL[row * NOUT];
    float x0 = x[tid];
    float x1 = x[tid + 256];
    float x2 = (tid == 0) ? x[512] : 0.f;
    __shared__ float sh[8];

    float v = x0 + x1 + x2;
#pragma unroll
    for (int o = 16; o; o >>= 1) v += __shfl_xor_sync(0xffffffffu, v, o);
    if ((tid & 31) == 0) sh[tid >> 5] = v;
    __syncthreads();
    float mean = 0.f;
#pragma unroll
    for (int i = 0; i < 8; i++) mean += sh[i];
    mean *= (1.f / 513.f);
    __syncthreads();

    float d0 = x0 - mean, d1 = x1 - mean, d2 = x2 - mean;
    v = d0 * d0 + d1 * d1 + ((tid == 0) ? d2 * d2 : 0.f);
#pragma unroll
    for (int o = 16; o; o >>= 1) v += __shfl_xor_sync(0xffffffffu, v, o);
    if ((tid & 31) == 0) sh[tid >> 5] = v;
    __syncthreads();
    float var = 0.f;
#pragma unroll
    for (int i = 0; i < 8; i++) var += sh[i];
    var *= (1.f / 513.f);
    float rstd = rsqrtf(var + 1e-5f);

    float qv = d0 * rstd * lnw[tid] + lnb[tid];
    float kv = d1 * rstd * lnw[tid + 256] + lnb[tid + 256];
    g_Q[row * DIMH + tid] = qv;
    g_K[row * DIMH + tid] = kv;
    g_Qh[row * DIMH + tid] = __float2bfloat16_rn(qv);
    g_Kh[row * DIMH + tid] = __float2bfloat16_rn(kv);
    if (tid == 0) g_logit[row] = d2 * rstd * lnw[512] + lnb[512];
}

// ---------------- kernel C: scatter-add weights ----------------
__global__ void __launch_bounds__(256) scatter_kernel(const float* __restrict__ wts,
                                                      const int* __restrict__ ii) {
    int e = blockIdx.x * 256 + threadIdx.x;
    if (e < EPAIR) atomicAdd(&g_Wall[ii[e]], wts[e]);
}

// ---------------- kernel D: causal attention partial LSE (bf16 tensor cores) ----------------
// job = (seg, rowblock rb: 128 rows, keyblock ch: 128 cols), ch <= rb
__global__ void __launch_bounds__(256) attn_bf16() {
    int bx = blockIdx.x;
    int seg = bx / 36;
    int jid = bx - seg * 36;
    int rb = JOB_RB[jid];
    int ch = JOB_CH[jid];

    __shared__ uint32_t Qp[128][20];   // bf16 pairs, pad 16->20 (conflict-free frags)
    __shared__ uint32_t Kp[128][20];
    const int tid = threadIdx.x;
    const int wid = tid >> 5, lane = tid & 31;
    const int g = lane >> 2, tig = lane & 3;
    const int base = seg * SEGL;

    const uint32_t* Qg = (const uint32_t*)&g_Qh[0];  // [8192][128] pairs
    const uint32_t* Kg = (const uint32_t*)&g_Kh[0];

    float acc[16][4];
#pragma unroll
    for (int nt = 0; nt < 16; nt++)
#pragma unroll
        for (int e = 0; e < 4; e++) acc[nt][e] = 0.f;

    for (int kc = 0; kc < 8; kc++) {          // 8 chunks of 32 k (16 pairs)
#pragma unroll
        for (int i = 0; i < 2; i++) {
            int idx = tid + i * 256;          // 0..511
            int r = idx >> 2, j = idx & 3;    // row, uint4 within 16-pair row
            uint4 q = *(const uint4*)&Qg[(base + rb * 128 + r) * 128 + kc * 16 + j * 4];
            uint4 k = *(const uint4*)&Kg[(base + ch * 128 + r) * 128 + kc * 16 + j * 4];
            *(uint4*)&Qp[r][j * 4] = q;
            *(uint4*)&Kp[r][j * 4] = k;
        }
        __syncthreads();
#pragma unroll
        for (int s = 0; s < 2; s++) {         // two k16 steps
            int kb = s * 8;
            uint32_t a0 = Qp[wid * 16 + g][kb + tig];
            uint32_t a1 = Qp[wid * 16 + g + 8][kb + tig];
            uint32_t a2 = Qp[wid * 16 + g][kb + tig + 4];
            uint32_t a3 = Qp[wid * 16 + g + 8][kb + tig + 4];
#pragma unroll
            for (int nt = 0; nt < 16; nt++) {
                uint32_t b0 = Kp[nt * 8 + g][kb + tig];
                uint32_t b1 = Kp[nt * 8 + g][kb + tig + 4];
                mma_bf16(acc[nt], a0, a1, a2, a3, b0, b1);
            }
        }
        __syncthreads();
    }

    // epilogue: causal mask + per-row logsumexp partials (uniform control flow)
    const int pbase = ((seg * 8 + rb) * 8 + ch) * 128;
    const int rin0 = wid * 16 + g;
#pragma unroll
    for (int h = 0; h < 2; h++) {
        int rin = rin0 + h * 8;
        int irow = rb * 128 + rin;            // row index within segment
        float mx = -INFINITY;
#pragma unroll
        for (int nt = 0; nt < 16; nt++) {
#pragma unroll
            for (int e = 0; e < 2; e++) {
                int jcol = ch * 128 + nt * 8 + tig * 2 + e;
                float v = acc[nt][h * 2 + e];
                if (jcol >= irow) v = -INFINITY;
                acc[nt][h * 2 + e] = v;
                mx = fmaxf(mx, v);
            }
        }
        mx = fmaxf(mx, __shfl_xor_sync(0xffffffffu, mx, 1));
        mx = fmaxf(mx, __shfl_xor_sync(0xffffffffu, mx, 2));
        float mb = fmaxf(mx, -3.0e38f);
        float s = 0.f;
#pragma unroll
        for (int nt = 0; nt < 16; nt++) {
            s += __expf(acc[nt][h * 2 + 0] - mb);
            s += __expf(acc[nt][h * 2 + 1] - mb);
        }
        s += __shfl_xor_sync(0xffffffffu, s, 1);
        s += __shfl_xor_sync(0xffffffffu, s, 2);
        if (tig == 0) {
            g_partM[pbase + rin] = mx;
            g_partL[pbase + rin] = s;
        }
    }
}

// ---------------- kernel D2: merge chunk partials into logZ ----------------
__global__ void __launch_bounds__(256) combine_kernel() {
    int i = blockIdx.x * 256 + threadIdx.x;
    if (i >= N_TOK) return;
    int seg = i >> 10;
    int r = i & 1023;
    int rb = r >> 7;
    int rr = r & 127;
    int nch = rb + 1;
    float M = -INFINITY, L = 0.f;
    for (int ch = 0; ch < nch; ch++) {
        int p = ((seg * 8 + rb) * 8 + ch) * 128 + rr;
        float m = g_partM[p];
        float l = g_partL[p];
        if (l > 0.f) {
            if (m > M) { L = L * __expf(M - m) + l; M = m; }
            else        { L += l * __expf(m - M); }
        }
    }
    g_logZ[i] = (L > 0.f) ? (M + logf(L)) : -INFINITY;
}

// ---------------- kernel E: sum_e w[e] * (Q[i[e]] . K[j[e]])  (fp32 exact) ----------------
__global__ void __launch_bounds__(256) cond_kernel(const float* __restrict__ wts,
                                                   const int* __restrict__ ii,
                                                   const int* __restrict__ jj) {
    int tid = threadIdx.x;
    int lane = tid & 31;
    int warp = tid >> 5;
    int gw = blockIdx.x * 8 + warp;
    double acc = 0.0;
    for (int e = gw; e < EPAIR; e += 2048) {
        int i = ii[e], j = jj[e];
        const float4* q = (const float4*)&g_Q[i * DIMH];
        const float4* k = (const float4*)&g_K[j * DIMH];
        float4 qa = q[lane * 2], qb = q[lane * 2 + 1];
        float4 ka = k[lane * 2], kb = k[lane * 2 + 1];
        float d = qa.x * ka.x + qa.y * ka.y + qa.z * ka.z + qa.w * ka.w
                + qb.x * kb.x + qb.y * kb.y + qb.z * kb.z + qb.w * kb.w;
#pragma unroll
        for (int o = 16; o; o >>= 1) d += __shfl_xor_sync(0xffffffffu, d, o);
        if (lane == 0) acc += (double)wts[e] * (double)d;
    }
    __shared__ double shd[256];
    shd[tid] = acc;
    __syncthreads();
    for (int s = 128; s; s >>= 1) {
        if (tid < s) shd[tid] += shd[tid + s];
        __syncthreads();
    }
    if (tid == 0) atomicAdd(&g_accCond, shd[0]);
}

// ---------------- kernel F: per-segment logsumexp of logit ----------------
__global__ void __launch_bounds__(256) zseg_kernel() {
    int seg = blockIdx.x;
    int tid = threadIdx.x;
    const float* lp = &g_logit[seg * SEGL];
    float vals[4];
    float mx = -INFINITY;
#pragma unroll
    for (int q = 0; q < 4; q++) { vals[q] = lp[tid + q * 256]; mx = fmaxf(mx, vals[q]); }
    __shared__ float sh[8];
#pragma unroll
    for (int o = 16; o; o >>= 1) mx = fmaxf(mx, __shfl_xor_sync(0xffffffffu, mx, o));
    if ((tid & 31) == 0) sh[tid >> 5] = mx;
    __syncthreads();
    float bm = -INFINITY;
#pragma unroll
    for (int i = 0; i < 8; i++) bm = fmaxf(bm, sh[i]);
    __syncthreads();
    float s = 0.f;
#pragma unroll
    for (int q = 0; q < 4; q++) s += expf(vals[q] - bm);
#pragma unroll
    for (int o = 16; o; o >>= 1) s += __shfl_xor_sync(0xffffffffu, s, o);
    if ((tid & 31) == 0) sh[tid >> 5] = s;
    __syncthreads();
    if (tid == 0) {
        float tot = 0.f;
#pragma unroll
        for (int i = 0; i < 8; i++) tot += sh[i];
        g_z[seg] = bm + logf(tot);
    }
}

// ---------------- kernel G: final reduction ----------------
__global__ void __launch_bounds__(256) final_kernel(float* __restrict__ out) {
    int tid = threadIdx.x;
    double acc = 0.0;
    for (int i = tid; i < N_TOK; i += 256) {
        float w = g_Wall[i];
        if (w > 0.f) {
            int seg = i >> 10;
            acc += (double)w * ((double)g_logit[i] - (double)g_z[seg] - (double)g_logZ[i]);
        }
    }
    __shared__ double shd[256];
    shd[tid] = acc;
    __syncthreads();
    for (int s = 128; s; s >>= 1) {
        if (tid < s) shd[tid] += shd[tid + s];
        __syncthreads();
    }
    if (tid == 0) out[0] = -(float)(g_accCond + shd[0]);
}

// ---------------- launch ----------------
extern "C" void kernel_launch(void* const* d_in, const int* in_sizes, int n_in,
                              void* d_out, int out_size) {
    const float* hidden = (const float*)d_in[0];
    const float* Wp     = (const float*)d_in[1];
    const float* bp     = (const float*)d_in[2];
    const float* lnw    = (const float*)d_in[3];
    const float* lnb    = (const float*)d_in[4];
    const float* wts    = (const float*)d_in[5];
    const int*   ii     = (const int*)d_in[6];
    const int*   jj     = (const int*)d_in[7];
    float* out = (float*)d_out;

    zero_kernel<<<32, 256>>>();
    proj_gemm_tc<<<dim3(9, 64), 256>>>(hidden, Wp, bp);
    ln_kernel<<<N_TOK, 256>>>(lnw, lnb);
    scatter_kernel<<<256, 256>>>(wts, ii);
    attn_bf16<<<288, 256>>>();
    combine_kernel<<<32, 256>>>();
    cond_kernel<<<256, 256>>>(wts, ii, jj);
    zseg_kernel<<<NSEG, 256>>>();
    final_kernel<<<1, 256>>>(out);
}

// round 7
// speedup vs baseline: 2.8284x; 1.0784x over previous
#include <cuda_runtime.h>
#include <cuda_bf16.h>
#include <math.h>
#include <stdint.h>

#define N_TOK 8192
#define DIMH  256
#define NOUT  513
#define SEGL  1024
#define NSEG  8
#define EPAIR 65536

// ---------------- scratch (static device memory; no allocations) ----------------
__device__ float  g_QKL[N_TOK * NOUT];
__device__ float  g_Q[N_TOK * DIMH];
__device__ float  g_K[N_TOK * DIMH];
__device__ __nv_bfloat16 g_Qh[N_TOK * DIMH];
__device__ __nv_bfloat16 g_Kh[N_TOK * DIMH];
__device__ float  g_logit[N_TOK];
__device__ float  g_Wall[N_TOK];
__device__ float  g_logZ[N_TOK];
__device__ float  g_partM[NSEG * 8 * 8 * 128];   // (seg, rb, chunk, row)
__device__ float  g_partL[NSEG * 8 * 8 * 128];
__device__ float  g_z[NSEG];
__device__ double g_accCond;

// 36 jobs per segment: rowblock rb (128 rows) x keyblock ch (128 cols), ch <= rb
__constant__ unsigned char JOB_RB[36] = {
    0, 1,1, 2,2,2, 3,3,3,3, 4,4,4,4,4, 5,5,5,5,5,5,
    6,6,6,6,6,6,6, 7,7,7,7,7,7,7,7};
__constant__ unsigned char JOB_CH[36] = {
    0, 0,1, 0,1,2, 0,1,2,3, 0,1,2,3,4, 0,1,2,3,4,5,
    0,1,2,3,4,5,6, 0,1,2,3,4,5,6,7};

// ---------------- mma helpers ----------------
__device__ __forceinline__ uint32_t tf32cvt(float x) {
    uint32_t r; asm("cvt.rna.tf32.f32 %0, %1;" : "=r"(r) : "f"(x)); return r;
}
__device__ __forceinline__ void mma_tf32(float* c, uint32_t a0, uint32_t a1,
                                         uint32_t a2, uint32_t a3,
                                         uint32_t b0, uint32_t b1) {
    asm("mma.sync.aligned.m16n8k8.row.col.f32.tf32.tf32.f32 "
        "{%0,%1,%2,%3},{%4,%5,%6,%7},{%8,%9},{%0,%1,%2,%3};"
        : "+f"(c[0]), "+f"(c[1]), "+f"(c[2]), "+f"(c[3])
        : "r"(a0), "r"(a1), "r"(a2), "r"(a3), "r"(b0), "r"(b1));
}
__device__ __forceinline__ void mma_bf16(float* c, uint32_t a0, uint32_t a1,
                                         uint32_t a2, uint32_t a3,
                                         uint32_t b0, uint32_t b1) {
    asm("mma.sync.aligned.m16n8k16.row.col.f32.bf16.bf16.f32 "
        "{%0,%1,%2,%3},{%4,%5,%6,%7},{%8,%9},{%0,%1,%2,%3};"
        : "+f"(c[0]), "+f"(c[1]), "+f"(c[2]), "+f"(c[3])
        : "r"(a0), "r"(a1), "r"(a2), "r"(a3), "r"(b0), "r"(b1));
}

// ---------------- kernel 0: zero accumulators ----------------
__global__ void __launch_bounds__(256) zero_kernel() {
    int i = blockIdx.x * 256 + threadIdx.x;
    if (i < N_TOK) g_Wall[i] = 0.f;
    if (i == 0) g_accCond = 0.0;
}

// ---------------- kernel A: projection GEMM (tf32, 128x128 tile) ----------------
__global__ void __launch_bounds__(256) proj_gemm_tc(const float* __restrict__ A,
                                                    const float* __restrict__ W,
                                                    const float* __restrict__ bias) {
    __shared__ uint32_t As[128][36];
    __shared__ uint32_t Bs[128][36];
    const int m0 = blockIdx.y * 128;
    const int n0 = blockIdx.x * 128;
    const int tid = threadIdx.x;
    const int wid = tid >> 5, lane = tid & 31;
    const int g = lane >> 2, tig = lane & 3;

    float acc[16][4];
#pragma unroll
    for (int nt = 0; nt < 16; nt++)
#pragma unroll
        for (int e = 0; e < 4; e++) acc[nt][e] = 0.f;

    for (int k0 = 0; k0 < DIMH; k0 += 32) {
#pragma unroll
        for (int i = 0; i < 4; i++) {
            int idx = tid + i * 256;            // 0..1023
            int r = idx >> 3, c4 = (idx & 7) * 4;
            float4 v = *(const float4*)&A[(m0 + r) * DIMH + k0 + c4];
            As[r][c4 + 0] = tf32cvt(v.x); As[r][c4 + 1] = tf32cvt(v.y);
            As[r][c4 + 2] = tf32cvt(v.z); As[r][c4 + 3] = tf32cvt(v.w);
            int n = n0 + r;
            float4 b = (n < NOUT) ? *(const float4*)&W[n * DIMH + k0 + c4]
                                  : make_float4(0.f, 0.f, 0.f, 0.f);
            Bs[r][c4 + 0] = tf32cvt(b.x); Bs[r][c4 + 1] = tf32cvt(b.y);
            Bs[r][c4 + 2] = tf32cvt(b.z); Bs[r][c4 + 3] = tf32cvt(b.w);
        }
        __syncthreads();
#pragma unroll
        for (int ks = 0; ks < 4; ks++) {
            int kb = ks * 8;
            uint32_t a0 = As[wid * 16 + g][kb + tig];
            uint32_t a1 = As[wid * 16 + g + 8][kb + tig];
            uint32_t a2 = As[wid * 16 + g][kb + tig + 4];
            uint32_t a3 = As[wid * 16 + g + 8][kb + tig + 4];
#pragma unroll
            for (int nt = 0; nt < 16; nt++) {
                uint32_t b0 = Bs[nt * 8 + g][kb + tig];
                uint32_t b1 = Bs[nt * 8 + g][kb + tig + 4];
                mma_tf32(acc[nt], a0, a1, a2, a3, b0, b1);
            }
        }
        __syncthreads();
    }

    const int r0 = m0 + wid * 16 + g;
#pragma unroll
    for (int nt = 0; nt < 16; nt++) {
        int c0 = n0 + nt * 8 + tig * 2;
        if (c0 < NOUT) {
            float bv = bias[c0];
            g_QKL[r0 * NOUT + c0] = acc[nt][0] + bv;
            g_QKL[(r0 + 8) * NOUT + c0] = acc[nt][2] + bv;
        }
        if (c0 + 1 < NOUT) {
            float bv = bias[c0 + 1];
            g_QKL[r0 * NOUT + c0 + 1] = acc[nt][1] + bv;
            g_QKL[(r0 + 8) * NOUT + c0 + 1] = acc[nt][3] + bv;
        }
    }
}

// ---------------- kernel B: warp-per-row layernorm (no smem, no block sync) ----------------
// lane covers cols {lane + 32t : t=0..15}; t<8 -> Q half, t>=8 -> K half.
__global__ void __launch_bounds__(256) ln_warp(const float* __restrict__ lnw,
                                               const float* __restrict__ lnb) {
    const int row = blockIdx.x * 8 + (threadIdx.x >> 5);
    const int lane = threadIdx.x & 31;
    const float* x = &g_QKL[row * NOUT];

    float xv[16];
#pragma unroll
    for (int t = 0; t < 16; t++) xv[t] = x[lane + 32 * t];
    float x512 = x[512];                       // broadcast load

    float sum = (lane == 0) ? x512 : 0.f;
    float sq  = (lane == 0) ? x512 * x512 : 0.f;
#pragma unroll
    for (int t = 0; t < 16; t++) { sum += xv[t]; sq += xv[t] * xv[t]; }
#pragma unroll
    for (int o = 16; o; o >>= 1) {
        sum += __shfl_xor_sync(0xffffffffu, sum, o);
        sq  += __shfl_xor_sync(0xffffffffu, sq, o);
    }
    float mean = sum * (1.f / 513.f);
    float var  = sq * (1.f / 513.f) - mean * mean;
    float rstd = rsqrtf(var + 1e-5f);

#pragma unroll
    for (int t = 0; t < 8; t++) {             // Q half: cols lane+32t (0..255)
        int c = lane + 32 * t;
        float qv = (xv[t] - mean) * rstd * lnw[c] + lnb[c];
        g_Q[row * DIMH + c] = qv;
        g_Qh[row * DIMH + c] = __float2bfloat16_rn(qv);
    }
#pragma unroll
    for (int t = 0; t < 8; t++) {             // K half: cols 256+lane+32t
        int c = lane + 32 * t;
        float kv = (xv[t + 8] - mean) * rstd * lnw[256 + c] + lnb[256 + c];
        g_K[row * DIMH + c] = kv;
        g_Kh[row * DIMH + c] = __float2bfloat16_rn(kv);
    }
    if (lane == 0)
        g_logit[row] = (x512 - mean) * rstd * lnw[512] + lnb[512];
}

// ---------------- kernel D: causal attention partial LSE (bf16 tensor cores) ----------------
__global__ void __launch_bounds__(256) attn_bf16() {
    int bx = blockIdx.x;
    int seg = bx / 36;
    int jid = bx - seg * 36;
    int rb = JOB_RB[jid];
    int ch = JOB_CH[jid];

    __shared__ uint32_t Qp[128][20];
    __shared__ uint32_t Kp[128][20];
    const int tid = threadIdx.x;
    const int wid = tid >> 5, lane = tid & 31;
    const int g = lane >> 2, tig = lane & 3;
    const int base = seg * SEGL;

    const uint32_t* Qg = (const uint32_t*)&g_Qh[0];
    const uint32_t* Kg = (const uint32_t*)&g_Kh[0];

    float acc[16][4];
#pragma unroll
    for (int nt = 0; nt < 16; nt++)
#pragma unroll
        for (int e = 0; e < 4; e++) acc[nt][e] = 0.f;

    for (int kc = 0; kc < 8; kc++) {
#pragma unroll
        for (int i = 0; i < 2; i++) {
            int idx = tid + i * 256;
            int r = idx >> 2, j = idx & 3;
            uint4 q = *(const uint4*)&Qg[(base + rb * 128 + r) * 128 + kc * 16 + j * 4];
            uint4 k = *(const uint4*)&Kg[(base + ch * 128 + r) * 128 + kc * 16 + j * 4];
            *(uint4*)&Qp[r][j * 4] = q;
            *(uint4*)&Kp[r][j * 4] = k;
        }
        __syncthreads();
#pragma unroll
        for (int s = 0; s < 2; s++) {
            int kb = s * 8;
            uint32_t a0 = Qp[wid * 16 + g][kb + tig];
            uint32_t a1 = Qp[wid * 16 + g + 8][kb + tig];
            uint32_t a2 = Qp[wid * 16 + g][kb + tig + 4];
            uint32_t a3 = Qp[wid * 16 + g + 8][kb + tig + 4];
#pragma unroll
            for (int nt = 0; nt < 16; nt++) {
                uint32_t b0 = Kp[nt * 8 + g][kb + tig];
                uint32_t b1 = Kp[nt * 8 + g][kb + tig + 4];
                mma_bf16(acc[nt], a0, a1, a2, a3, b0, b1);
            }
        }
        __syncthreads();
    }

    const int pbase = ((seg * 8 + rb) * 8 + ch) * 128;
    const int rin0 = wid * 16 + g;
#pragma unroll
    for (int h = 0; h < 2; h++) {
        int rin = rin0 + h * 8;
        int irow = rb * 128 + rin;
        float mx = -INFINITY;
#pragma unroll
        for (int nt = 0; nt < 16; nt++) {
#pragma unroll
            for (int e = 0; e < 2; e++) {
                int jcol = ch * 128 + nt * 8 + tig * 2 + e;
                float v = acc[nt][h * 2 + e];
                if (jcol >= irow) v = -INFINITY;
                acc[nt][h * 2 + e] = v;
                mx = fmaxf(mx, v);
            }
        }
        mx = fmaxf(mx, __shfl_xor_sync(0xffffffffu, mx, 1));
        mx = fmaxf(mx, __shfl_xor_sync(0xffffffffu, mx, 2));
        float mb = fmaxf(mx, -3.0e38f);
        float s = 0.f;
#pragma unroll
        for (int nt = 0; nt < 16; nt++) {
            s += __expf(acc[nt][h * 2 + 0] - mb);
            s += __expf(acc[nt][h * 2 + 1] - mb);
        }
        s += __shfl_xor_sync(0xffffffffu, s, 1);
        s += __shfl_xor_sync(0xffffffffu, s, 2);
        if (tig == 0) {
            g_partM[pbase + rin] = mx;
            g_partL[pbase + rin] = s;
        }
    }
}

// ---------------- kernel D2: merge partials into logZ + per-seg logit LSE ----------------
// blocks 0..31: combine logZ; blocks 32..39: zseg for segment (bx-32)
__global__ void __launch_bounds__(256) combine_zseg() {
    int bx = blockIdx.x;
    int tid = threadIdx.x;
    if (bx < 32) {
        int i = bx * 256 + tid;
        int seg = i >> 10;
        int r = i & 1023;
        int rb = r >> 7;
        int rr = r & 127;
        int nch = rb + 1;
        float M = -INFINITY, L = 0.f;
        for (int ch = 0; ch < nch; ch++) {
            int p = ((seg * 8 + rb) * 8 + ch) * 128 + rr;
            float m = g_partM[p];
            float l = g_partL[p];
            if (l > 0.f) {
                if (m > M) { L = L * __expf(M - m) + l; M = m; }
                else        { L += l * __expf(m - M); }
            }
        }
        g_logZ[i] = (L > 0.f) ? (M + logf(L)) : -INFINITY;
    } else {
        int seg = bx - 32;
        const float* lp = &g_logit[seg * SEGL];
        float vals[4];
        float mx = -INFINITY;
#pragma unroll
        for (int q = 0; q < 4; q++) { vals[q] = lp[tid + q * 256]; mx = fmaxf(mx, vals[q]); }
        __shared__ float sh[8];
#pragma unroll
        for (int o = 16; o; o >>= 1) mx = fmaxf(mx, __shfl_xor_sync(0xffffffffu, mx, o));
        if ((tid & 31) == 0) sh[tid >> 5] = mx;
        __syncthreads();
        float bm = -INFINITY;
#pragma unroll
        for (int i2 = 0; i2 < 8; i2++) bm = fmaxf(bm, sh[i2]);
        __syncthreads();
        float s = 0.f;
#pragma unroll
        for (int q = 0; q < 4; q++) s += expf(vals[q] - bm);
#pragma unroll
        for (int o = 16; o; o >>= 1) s += __shfl_xor_sync(0xffffffffu, s, o);
        if ((tid & 31) == 0) sh[tid >> 5] = s;
        __syncthreads();
        if (tid == 0) {
            float tot = 0.f;
#pragma unroll
            for (int i2 = 0; i2 < 8; i2++) tot += sh[i2];
            g_z[seg] = bm + logf(tot);
        }
    }
}

// ---------------- kernel E: conditional sum + weight scatter (bf16 gathers) ----------------
__global__ void __launch_bounds__(256) cond_scatter(const float* __restrict__ wts,
                                                    const int* __restrict__ ii,
                                                    const int* __restrict__ jj) {
    int tid = threadIdx.x;
    int lane = tid & 31;
    int warp = tid >> 5;
    int gw = blockIdx.x * 8 + warp;
    const uint4* Qg = (const uint4*)&g_Qh[0];   // row = 32 uint4
    const uint4* Kg = (const uint4*)&g_Kh[0];
    double acc = 0.0;
    for (int e = gw; e < EPAIR; e += 2048) {
        int i = ii[e], j = jj[e];
        uint4 qu = Qg[i * 32 + lane];
        uint4 ku = Kg[j * 32 + lane];
        float d = 0.f;
        const uint32_t* qw = (const uint32_t*)&qu;
        const uint32_t* kw = (const uint32_t*)&ku;
#pragma unroll
        for (int w = 0; w < 4; w++) {
            float2 qf = __bfloat1622float2(*(const __nv_bfloat162*)&qw[w]);
            float2 kf = __bfloat1622float2(*(const __nv_bfloat162*)&kw[w]);
            d += qf.x * kf.x + qf.y * kf.y;
        }
#pragma unroll
        for (int o = 16; o; o >>= 1) d += __shfl_xor_sync(0xffffffffu, d, o);
        if (lane == 0) {
            float w = wts[e];
            acc += (double)w * (double)d;
            atomicAdd(&g_Wall[i], w);
        }
    }
    __shared__ double shd[256];
    shd[tid] = acc;
    __syncthreads();
    for (int s = 128; s; s >>= 1) {
        if (tid < s) shd[tid] += shd[tid + s];
        __syncthreads();
    }
    if (tid == 0) atomicAdd(&g_accCond, shd[0]);
}

// ---------------- kernel G: final reduction ----------------
__global__ void __launch_bounds__(256) final_kernel(float* __restrict__ out) {
    int tid = threadIdx.x;
    double acc = 0.0;
    for (int i = tid; i < N_TOK; i += 256) {
        float w = g_Wall[i];
        if (w > 0.f) {
            int seg = i >> 10;
            acc += (double)w * ((double)g_logit[i] - (double)g_z[seg] - (double)g_logZ[i]);
        }
    }
    __shared__ double shd[256];
    shd[tid] = acc;
    __syncthreads();
    for (int s = 128; s; s >>= 1) {
        if (tid < s) shd[tid] += shd[tid + s];
        __syncthreads();
    }
    if (tid == 0) out[0] = -(float)(g_accCond + shd[0]);
}

// ---------------- launch ----------------
extern "C" void kernel_launch(void* const* d_in, const int* in_sizes, int n_in,
                              void* d_out, int out_size) {
    const float* hidden = (const float*)d_in[0];
    const float* Wp     = (const float*)d_in[1];
    const float* bp     = (const float*)d_in[2];
    const float* lnw    = (const float*)d_in[3];
    const float* lnb    = (const float*)d_in[4];
    const float* wts    = (const float*)d_in[5];
    const int*   ii     = (const int*)d_in[6];
    const int*   jj     = (const int*)d_in[7];
    float* out = (float*)d_out;

    zero_kernel<<<32, 256>>>();
    proj_gemm_tc<<<dim3(5, 64), 256>>>(hidden, Wp, bp);
    ln_warp<<<1024, 256>>>(lnw, lnb);
    attn_bf16<<<288, 256>>>();
    combine_zseg<<<40, 256>>>();
    cond_scatter<<<256, 256>>>(wts, ii, jj);
    final_kernel<<<1, 256>>>(out);
}